// round 12
// baseline (speedup 1.0000x reference)
#include <cuda_runtime.h>
#include <cuda_fp16.h>
#include <math.h>

// CGCNN on GB300. fp16 tables/h, HFMA2 math, fused state re-zeroing,
// 4-edge ILP edge pass, stats+bnfin fused (last-block), pool fused into upd.

#define NN 100000
#define EE 1600000
#define BB 256
#define FN 35
#define FE 10

__device__ float g_h[NN * 64];
__device__ __half g_hh[NN * 64];
__device__ __half g_Tsh[NN * 128];
__device__ __half g_Tdh[NN * 128];
__device__ float g_agg[NN * 64];      // static zero-init; re-zeroed by upd_k
__device__ float g_stats[128];        // re-zeroed by stats_k last block
__device__ float g_scale[64];
__device__ float g_shift[64];
__device__ float g_pool[BB * 64];     // re-zeroed by mlp_k
__device__ float g_cnt[BB];
__device__ int g_ctr;                 // stats last-block counter (reset each use)

__device__ __forceinline__ float fsoftplus(float x) {
    return fmaxf(x, 0.f) + __logf(1.f + __expf(-fabsf(x)));
}
__device__ __forceinline__ float fsigmoid(float x) {
    return __fdividef(1.f, 1.f + __expf(-x));
}
__device__ __forceinline__ void red_add_v4(float* p, float a, float b, float c, float d) {
    asm volatile("red.global.add.v4.f32 [%0], {%1, %2, %3, %4};"
                 :: "l"(p), "f"(a), "f"(b), "f"(c), "f"(d) : "memory");
}
__device__ __forceinline__ void red_add_f(float* p, float v) {
    asm volatile("red.global.add.f32 [%0], %1;" :: "l"(p), "f"(v) : "memory");
}

// ---------------- embed: h = nf @ ew + eb, 32 nodes/block ----------------
__global__ __launch_bounds__(256) void embed_k(const float* __restrict__ nf,
                                               const float* __restrict__ ew,
                                               const float* __restrict__ eb) {
    __shared__ float sw[FN * 64];
    __shared__ float sb[64];
    __shared__ float snf[32][FN + 1];
    int tid = threadIdx.x;
    for (int i = tid; i < FN * 64; i += 256) sw[i] = ew[i];
    if (tid < 64) sb[tid] = eb[tid];
    int n0 = blockIdx.x * 32;
    for (int i = tid; i < 32 * FN; i += 256) {
        int r = i / FN, c = i % FN;
        int n = n0 + r;
        snf[r][c] = (n < NN) ? nf[(size_t)n * FN + c] : 0.f;
    }
    __syncthreads();
    int r = tid >> 6, j = tid & 63;
#pragma unroll
    for (int ii = 0; ii < 8; ii++) {
        int rr = r + ii * 4;
        int n = n0 + rr;
        if (n < NN) {
            float acc = sb[j];
#pragma unroll
            for (int k = 0; k < FN; k++) acc = fmaf(snf[rr][k], sw[k * 64 + j], acc);
            g_h[(size_t)n * 64 + j] = acc;
            g_hh[(size_t)n * 64 + j] = __float2half(acc);
        }
    }
}

// ---------------- node transform -> fp16 tables, HFMA2 ----------
#define NT_TILE 128
__global__ __launch_bounds__(256) void nodetf_k(
    const float* __restrict__ gw, const float* __restrict__ cw,
    const float* __restrict__ gb, const float* __restrict__ cb) {
    __shared__ __half hs[NT_TILE * 64];
    int c = threadIdx.x;
    const float* wbase;
    int cc, krow0;
    float bias = 0.f;
    if (c < 64)       { wbase = gw; cc = c;       krow0 = 0;  }
    else if (c < 128) { wbase = cw; cc = c - 64;  krow0 = 0;  }
    else if (c < 192) { wbase = gw; cc = c - 128; krow0 = 64; bias = gb[cc]; }
    else              { wbase = cw; cc = c - 192; krow0 = 64; bias = cb[cc]; }
    __half2 w2[32];
#pragma unroll
    for (int k2 = 0; k2 < 32; k2++)
        w2[k2] = __floats2half2_rn(wbase[(krow0 + 2 * k2) * 64 + cc],
                                   wbase[(krow0 + 2 * k2 + 1) * 64 + cc]);
    __half* tbl = (c < 128) ? (g_Tsh + c) : (g_Tdh + (c - 128));

    int n0 = blockIdx.x * NT_TILE;
#pragma unroll
    for (int i = 0; i < NT_TILE / 32; i++) {
        int idx = c + i * 256;
        int n = n0 + (idx >> 3);
        uint4 z = make_uint4(0u, 0u, 0u, 0u);
        ((uint4*)hs)[idx] = (n < NN) ? ((const uint4*)g_hh)[(size_t)n0 * 8 + idx] : z;
    }
    __syncthreads();

#pragma unroll 1
    for (int j0 = 0; j0 < NT_TILE; j0 += 4) {
        __half2 acc[4];
#pragma unroll
        for (int j = 0; j < 4; j++) acc[j] = __floats2half2_rn(0.f, 0.f);
#pragma unroll
        for (int k8 = 0; k8 < 8; k8++) {
#pragma unroll
            for (int j = 0; j < 4; j++) {
                uint4 hv = ((const uint4*)(hs + (j0 + j) * 64))[k8];
                __half2 h0 = *(__half2*)&hv.x;
                __half2 h1 = *(__half2*)&hv.y;
                __half2 h2 = *(__half2*)&hv.z;
                __half2 h3 = *(__half2*)&hv.w;
                acc[j] = __hfma2(h0, w2[4 * k8 + 0], acc[j]);
                acc[j] = __hfma2(h1, w2[4 * k8 + 1], acc[j]);
                acc[j] = __hfma2(h2, w2[4 * k8 + 2], acc[j]);
                acc[j] = __hfma2(h3, w2[4 * k8 + 3], acc[j]);
            }
        }
#pragma unroll
        for (int j = 0; j < 4; j++) {
            int n = n0 + j0 + j;
            if (n < NN) {
                float2 f = __half22float2(acc[j]);
                tbl[(size_t)n * 128] = __float2half(f.x + f.y + bias);
            }
        }
    }
}

// ---------------- edge pass: warp/edge, 4-edge ILP, HFMA2 ----------------
#define EPW 16
__global__ __launch_bounds__(256) void edge_k(
    const int* __restrict__ src, const int* __restrict__ dst,
    const float* __restrict__ ef,
    const float* __restrict__ gwE, const float* __restrict__ cwE) {
    __shared__ __half2 sef[128 * FE];
    int tid = threadIdx.x;
    int warp = tid >> 5;
    int l = tid & 31;

    __half2 wgh[FE], wch[FE];
#pragma unroll
    for (int k = 0; k < FE; k++) {
        wgh[k] = __floats2half2_rn(gwE[k * 64 + 2 * l], gwE[k * 64 + 2 * l + 1]);
        wch[k] = __floats2half2_rn(cwE[k * 64 + 2 * l], cwE[k * 64 + 2 * l + 1]);
    }

    int base = blockIdx.x * 128;
#pragma unroll
    for (int i = tid; i < 128 * FE; i += 256) {
        float v = __ldcs(&ef[(size_t)base * FE + i]);
        sef[i] = __half2half2(__float2half(v));
    }
    __syncthreads();

    int le = warp * EPW;
#pragma unroll 2
    for (int it = 0; it < EPW; it += 2, le += 2) {
        int e0 = base + le;
        int s0 = __ldcs(&src[e0]);
        int d0 = __ldcs(&dst[e0]);
        int s1 = __ldcs(&src[e0 + 1]);
        int d1 = __ldcs(&dst[e0 + 1]);
        const __half2* ts0 = (const __half2*)(g_Tsh + (size_t)s0 * 128);
        const __half2* td0 = (const __half2*)(g_Tdh + (size_t)d0 * 128);
        const __half2* ts1 = (const __half2*)(g_Tsh + (size_t)s1 * 128);
        const __half2* td1 = (const __half2*)(g_Tdh + (size_t)d1 * 128);
        __half2 a0 = ts0[l], u0 = ts0[32 + l], b0 = td0[l], v0 = td0[32 + l];
        __half2 a1 = ts1[l], u1 = ts1[32 + l], b1 = td1[l], v1 = td1[32 + l];
        __half2 x0 = __hadd2(a0, b0), y0 = __hadd2(u0, v0);
        __half2 x1 = __hadd2(a1, b1), y1 = __hadd2(u1, v1);
#pragma unroll
        for (int k = 0; k < FE; k++) {
            __half2 ev0 = sef[le * FE + k];
            __half2 ev1 = sef[(le + 1) * FE + k];
            x0 = __hfma2(ev0, wgh[k], x0);
            y0 = __hfma2(ev0, wch[k], y0);
            x1 = __hfma2(ev1, wgh[k], x1);
            y1 = __hfma2(ev1, wch[k], y1);
        }
        float2 xf0 = __half22float2(x0), yf0 = __half22float2(y0);
        float2 xf1 = __half22float2(x1), yf1 = __half22float2(y1);
        float m00 = fsigmoid(xf0.x) * fsoftplus(yf0.x);
        float m01 = fsigmoid(xf0.y) * fsoftplus(yf0.y);
        float m10 = fsigmoid(xf1.x) * fsoftplus(yf1.x);
        float m11 = fsigmoid(xf1.y) * fsoftplus(yf1.y);
        float p00 = __shfl_down_sync(0xffffffffu, m00, 1);
        float p01 = __shfl_down_sync(0xffffffffu, m01, 1);
        float p10 = __shfl_down_sync(0xffffffffu, m10, 1);
        float p11 = __shfl_down_sync(0xffffffffu, m11, 1);
        if ((l & 1) == 0) {
            red_add_v4(g_agg + (size_t)s0 * 64 + 2 * l, m00, m01, p00, p01);
            red_add_v4(g_agg + (size_t)s1 * 64 + 2 * l, m10, m11, p10, p11);
        }
    }
}

// ------- BN stats + finalize fused (last block computes scale/shift) --------
#define STATS_GRID 1024
__global__ __launch_bounds__(256) void stats_k(const float* __restrict__ bg,
                                               const float* __restrict__ bb) {
    int tid = threadIdx.x;
    int q = tid & 15;
    int r = tid >> 4;
    float4 s = make_float4(0.f, 0.f, 0.f, 0.f);
    float4 s2 = make_float4(0.f, 0.f, 0.f, 0.f);
    for (int n = blockIdx.x * 16 + r; n < NN; n += STATS_GRID * 16) {
        float4 v = ((const float4*)g_agg)[(size_t)n * 16 + q];
        s.x += v.x; s.y += v.y; s.z += v.z; s.w += v.w;
        s2.x += v.x * v.x; s2.y += v.y * v.y; s2.z += v.z * v.z; s2.w += v.w * v.w;
    }
    __shared__ float4 sh[256], sh2[256];
    sh[tid] = s; sh2[tid] = s2;
    __syncthreads();
#pragma unroll
    for (int off = 128; off >= 16; off >>= 1) {
        if (tid < off) {
            float4 a = sh[tid + off], b = sh2[tid + off];
            sh[tid].x += a.x; sh[tid].y += a.y; sh[tid].z += a.z; sh[tid].w += a.w;
            sh2[tid].x += b.x; sh2[tid].y += b.y; sh2[tid].z += b.z; sh2[tid].w += b.w;
        }
        __syncthreads();
    }
    if (tid < 16) {
        float4 a = sh[tid], b = sh2[tid];
        atomicAdd(&g_stats[4 * tid + 0], a.x);
        atomicAdd(&g_stats[4 * tid + 1], a.y);
        atomicAdd(&g_stats[4 * tid + 2], a.z);
        atomicAdd(&g_stats[4 * tid + 3], a.w);
        atomicAdd(&g_stats[64 + 4 * tid + 0], b.x);
        atomicAdd(&g_stats[64 + 4 * tid + 1], b.y);
        atomicAdd(&g_stats[64 + 4 * tid + 2], b.z);
        atomicAdd(&g_stats[64 + 4 * tid + 3], b.w);
    }
    __threadfence();
    __shared__ int isLast;
    if (tid == 0) isLast = (atomicAdd(&g_ctr, 1) == STATS_GRID - 1);
    __syncthreads();
    if (isLast) {
        if (tid < 64) {
            float sv = g_stats[tid], sv2 = g_stats[64 + tid];
            float mean = sv * (1.f / NN);
            float var = sv2 * (1.f / NN) - mean * mean;
            float sc = bg[tid] * rsqrtf(fmaxf(var, 0.f) + 1e-5f);
            g_scale[tid] = sc;
            g_shift[tid] = bb[tid] - mean * sc;
            g_stats[tid] = 0.f;
            g_stats[64 + tid] = 0.f;
        }
        if (tid == 0) g_ctr = 0;
    }
}

// h = softplus(h + agg*scale + shift); re-zero agg; optional fused pooling
__global__ void upd_k(const int* __restrict__ gi, int doPool) {
    int i = blockIdx.x * 256 + threadIdx.x;
    if (i >= NN * 16) return;
    int j4 = (i & 15) * 4;
    float4 a = ((const float4*)g_agg)[i];
    ((float4*)g_agg)[i] = make_float4(0.f, 0.f, 0.f, 0.f);
    float4 h = ((const float4*)g_h)[i];
    float4 sc = *(const float4*)(g_scale + j4);
    float4 sf = *(const float4*)(g_shift + j4);
    h.x = fsoftplus(fmaf(a.x, sc.x, h.x + sf.x));
    h.y = fsoftplus(fmaf(a.y, sc.y, h.y + sf.y));
    h.z = fsoftplus(fmaf(a.z, sc.z, h.z + sf.z));
    h.w = fsoftplus(fmaf(a.w, sc.w, h.w + sf.w));
    if (doPool) {
        int n = i >> 4;
        int q = i & 15;
        int g = gi[n];
        red_add_v4(g_pool + g * 64 + 4 * q, h.x, h.y, h.z, h.w);
        if (q == 0) red_add_f(&g_cnt[g], 1.f);
    } else {
        ((float4*)g_h)[i] = h;
        __half2 h01 = __floats2half2_rn(h.x, h.y);
        __half2 h23 = __floats2half2_rn(h.z, h.w);
        uint2 packed;
        packed.x = *(unsigned*)&h01;
        packed.y = *(unsigned*)&h23;
        ((uint2*)g_hh)[i] = packed;
    }
}

// ---------------- final MLP; re-zeroes pool/cnt after reading ----------------
__global__ void mlp_k(const float* __restrict__ w1, const float* __restrict__ b1,
                      const float* __restrict__ w2, const float* __restrict__ b2,
                      const float* __restrict__ w3, const float* __restrict__ b3,
                      float* __restrict__ out) {
    int b = blockIdx.x;
    int t = threadIdx.x;  // 128 threads
    __shared__ float pm[64];
    __shared__ float s1[128];
    __shared__ float s2[64];
    __shared__ float red[128];
    if (t < 64) {
        float c = g_cnt[b];
        c = (c < 1.f) ? 1.f : c;
        pm[t] = g_pool[b * 64 + t] / c;
    }
    __syncthreads();
    if (t < 64) g_pool[b * 64 + t] = 0.f;
    if (t == 64) g_cnt[b] = 0.f;
    float a = b1[t];
#pragma unroll
    for (int k = 0; k < 64; k++) a = fmaf(pm[k], w1[k * 128 + t], a);
    s1[t] = fsoftplus(a);
    __syncthreads();
    if (t < 64) {
        float a2 = b2[t];
#pragma unroll
        for (int k = 0; k < 128; k++) a2 = fmaf(s1[k], w2[k * 64 + t], a2);
        s2[t] = fsoftplus(a2);
    }
    __syncthreads();
    float p = (t < 64) ? s2[t] * w3[t] : 0.f;
    red[t] = p;
    __syncthreads();
#pragma unroll
    for (int off = 64; off > 0; off >>= 1) {
        if (t < off) red[t] += red[t + off];
        __syncthreads();
    }
    if (t == 0) out[b] = red[0] + b3[0];
}

extern "C" void kernel_launch(void* const* d_in, const int* in_sizes, int n_in,
                              void* d_out, int out_size) {
    const float* nf  = (const float*)d_in[0];
    const int*   ei  = (const int*)d_in[1];
    const float* ef  = (const float*)d_in[2];
    const int*   gi  = (const int*)d_in[3];
    const float* ew  = (const float*)d_in[4];
    const float* eb  = (const float*)d_in[5];
    const float* gw  = (const float*)d_in[6];
    const float* gb  = (const float*)d_in[7];
    const float* cw  = (const float*)d_in[8];
    const float* cb  = (const float*)d_in[9];
    const float* bng = (const float*)d_in[10];
    const float* bnb = (const float*)d_in[11];
    const float* w1  = (const float*)d_in[12];
    const float* b1  = (const float*)d_in[13];
    const float* w2  = (const float*)d_in[14];
    const float* b2  = (const float*)d_in[15];
    const float* w3  = (const float*)d_in[16];
    const float* b3  = (const float*)d_in[17];
    float* out = (float*)d_out;
    const int* srcI = ei;
    const int* dstI = ei + EE;

    embed_k<<<(NN + 31) / 32, 256>>>(nf, ew, eb);
    for (int i = 0; i < 3; i++) {
        const float* gwi = gw + i * 138 * 64;
        const float* cwi = cw + i * 138 * 64;
        nodetf_k<<<(NN + NT_TILE - 1) / NT_TILE, 256>>>(gwi, cwi, gb + i * 64, cb + i * 64);
        edge_k<<<EE / 128, 256>>>(srcI, dstI, ef, gwi + 128 * 64, cwi + 128 * 64);
        stats_k<<<STATS_GRID, 256>>>(bng + i * 64, bnb + i * 64);
        upd_k<<<(NN * 16 + 255) / 256, 256>>>(gi, i == 2 ? 1 : 0);
    }
    mlp_k<<<BB, 128>>>(w1, b1, w2, b2, w3, b3, out);
}

// round 15
// speedup vs baseline: 1.0412x; 1.0412x over previous
#include <cuda_runtime.h>
#include <cuda_fp16.h>
#include <math.h>

// CGCNN on GB300. fp16 tables/h, HFMA2 math, fused state re-zeroing,
// 4-edge ILP edge pass, stats+bnfin fused (last-block, grid 256), pool fused into upd.

#define NN 100000
#define EE 1600000
#define BB 256
#define FN 35
#define FE 10

__device__ float g_h[NN * 64];
__device__ __half g_hh[NN * 64];
__device__ __half g_Tsh[NN * 128];
__device__ __half g_Tdh[NN * 128];
__device__ float g_agg[NN * 64];      // static zero-init; re-zeroed by upd_k
__device__ float g_stats[128];        // re-zeroed by stats_k last block
__device__ float g_scale[64];
__device__ float g_shift[64];
__device__ float g_pool[BB * 64];     // re-zeroed by mlp_k
__device__ float g_cnt[BB];
__device__ int g_ctr;                 // stats last-block counter (reset each use)

__device__ __forceinline__ float fsoftplus(float x) {
    return fmaxf(x, 0.f) + __logf(1.f + __expf(-fabsf(x)));
}
__device__ __forceinline__ float fsigmoid(float x) {
    return __fdividef(1.f, 1.f + __expf(-x));
}
__device__ __forceinline__ void red_add_v4(float* p, float a, float b, float c, float d) {
    asm volatile("red.global.add.v4.f32 [%0], {%1, %2, %3, %4};"
                 :: "l"(p), "f"(a), "f"(b), "f"(c), "f"(d) : "memory");
}
__device__ __forceinline__ void red_add_f(float* p, float v) {
    asm volatile("red.global.add.f32 [%0], %1;" :: "l"(p), "f"(v) : "memory");
}

// ---------------- embed: h = nf @ ew + eb, 32 nodes/block ----------------
__global__ __launch_bounds__(256) void embed_k(const float* __restrict__ nf,
                                               const float* __restrict__ ew,
                                               const float* __restrict__ eb) {
    __shared__ float sw[FN * 64];
    __shared__ float sb[64];
    __shared__ float snf[32][FN + 1];
    int tid = threadIdx.x;
    for (int i = tid; i < FN * 64; i += 256) sw[i] = ew[i];
    if (tid < 64) sb[tid] = eb[tid];
    int n0 = blockIdx.x * 32;
    for (int i = tid; i < 32 * FN; i += 256) {
        int r = i / FN, c = i % FN;
        int n = n0 + r;
        snf[r][c] = (n < NN) ? nf[(size_t)n * FN + c] : 0.f;
    }
    __syncthreads();
    int r = tid >> 6, j = tid & 63;
#pragma unroll
    for (int ii = 0; ii < 8; ii++) {
        int rr = r + ii * 4;
        int n = n0 + rr;
        if (n < NN) {
            float acc = sb[j];
#pragma unroll
            for (int k = 0; k < FN; k++) acc = fmaf(snf[rr][k], sw[k * 64 + j], acc);
            g_h[(size_t)n * 64 + j] = acc;
            g_hh[(size_t)n * 64 + j] = __float2half(acc);
        }
    }
}

// ---------------- node transform -> fp16 tables, HFMA2 ----------
#define NT_TILE 128
__global__ __launch_bounds__(256) void nodetf_k(
    const float* __restrict__ gw, const float* __restrict__ cw,
    const float* __restrict__ gb, const float* __restrict__ cb) {
    __shared__ __half hs[NT_TILE * 64];
    int c = threadIdx.x;
    const float* wbase;
    int cc, krow0;
    float bias = 0.f;
    if (c < 64)       { wbase = gw; cc = c;       krow0 = 0;  }
    else if (c < 128) { wbase = cw; cc = c - 64;  krow0 = 0;  }
    else if (c < 192) { wbase = gw; cc = c - 128; krow0 = 64; bias = gb[cc]; }
    else              { wbase = cw; cc = c - 192; krow0 = 64; bias = cb[cc]; }
    __half2 w2[32];
#pragma unroll
    for (int k2 = 0; k2 < 32; k2++)
        w2[k2] = __floats2half2_rn(wbase[(krow0 + 2 * k2) * 64 + cc],
                                   wbase[(krow0 + 2 * k2 + 1) * 64 + cc]);
    __half* tbl = (c < 128) ? (g_Tsh + c) : (g_Tdh + (c - 128));

    int n0 = blockIdx.x * NT_TILE;
#pragma unroll
    for (int i = 0; i < NT_TILE / 32; i++) {
        int idx = c + i * 256;
        int n = n0 + (idx >> 3);
        uint4 z = make_uint4(0u, 0u, 0u, 0u);
        ((uint4*)hs)[idx] = (n < NN) ? ((const uint4*)g_hh)[(size_t)n0 * 8 + idx] : z;
    }
    __syncthreads();

#pragma unroll 1
    for (int j0 = 0; j0 < NT_TILE; j0 += 4) {
        __half2 acc[4];
#pragma unroll
        for (int j = 0; j < 4; j++) acc[j] = __floats2half2_rn(0.f, 0.f);
#pragma unroll
        for (int k8 = 0; k8 < 8; k8++) {
#pragma unroll
            for (int j = 0; j < 4; j++) {
                uint4 hv = ((const uint4*)(hs + (j0 + j) * 64))[k8];
                __half2 h0 = *(__half2*)&hv.x;
                __half2 h1 = *(__half2*)&hv.y;
                __half2 h2 = *(__half2*)&hv.z;
                __half2 h3 = *(__half2*)&hv.w;
                acc[j] = __hfma2(h0, w2[4 * k8 + 0], acc[j]);
                acc[j] = __hfma2(h1, w2[4 * k8 + 1], acc[j]);
                acc[j] = __hfma2(h2, w2[4 * k8 + 2], acc[j]);
                acc[j] = __hfma2(h3, w2[4 * k8 + 3], acc[j]);
            }
        }
#pragma unroll
        for (int j = 0; j < 4; j++) {
            int n = n0 + j0 + j;
            if (n < NN) {
                float2 f = __half22float2(acc[j]);
                tbl[(size_t)n * 128] = __float2half(f.x + f.y + bias);
            }
        }
    }
}

// ---------------- edge pass: warp/edge, 4-edge ILP, HFMA2 ----------------
#define EPW 16
__global__ __launch_bounds__(256) void edge_k(
    const int* __restrict__ src, const int* __restrict__ dst,
    const float* __restrict__ ef,
    const float* __restrict__ gwE, const float* __restrict__ cwE) {
    __shared__ __half2 sef[128 * FE];
    int tid = threadIdx.x;
    int warp = tid >> 5;
    int l = tid & 31;

    __half2 wgh[FE], wch[FE];
#pragma unroll
    for (int k = 0; k < FE; k++) {
        wgh[k] = __floats2half2_rn(gwE[k * 64 + 2 * l], gwE[k * 64 + 2 * l + 1]);
        wch[k] = __floats2half2_rn(cwE[k * 64 + 2 * l], cwE[k * 64 + 2 * l + 1]);
    }

    int base = blockIdx.x * 128;
#pragma unroll
    for (int i = tid; i < 128 * FE; i += 256) {
        float v = __ldcs(&ef[(size_t)base * FE + i]);
        sef[i] = __half2half2(__float2half(v));
    }
    __syncthreads();

    int le = warp * EPW;
#pragma unroll 2
    for (int it = 0; it < EPW; it += 2, le += 2) {
        int e0 = base + le;
        int s0 = __ldcs(&src[e0]);
        int d0 = __ldcs(&dst[e0]);
        int s1 = __ldcs(&src[e0 + 1]);
        int d1 = __ldcs(&dst[e0 + 1]);
        const __half2* ts0 = (const __half2*)(g_Tsh + (size_t)s0 * 128);
        const __half2* td0 = (const __half2*)(g_Tdh + (size_t)d0 * 128);
        const __half2* ts1 = (const __half2*)(g_Tsh + (size_t)s1 * 128);
        const __half2* td1 = (const __half2*)(g_Tdh + (size_t)d1 * 128);
        __half2 a0 = ts0[l], u0 = ts0[32 + l], b0 = td0[l], v0 = td0[32 + l];
        __half2 a1 = ts1[l], u1 = ts1[32 + l], b1 = td1[l], v1 = td1[32 + l];
        __half2 x0 = __hadd2(a0, b0), y0 = __hadd2(u0, v0);
        __half2 x1 = __hadd2(a1, b1), y1 = __hadd2(u1, v1);
#pragma unroll
        for (int k = 0; k < FE; k++) {
            __half2 ev0 = sef[le * FE + k];
            __half2 ev1 = sef[(le + 1) * FE + k];
            x0 = __hfma2(ev0, wgh[k], x0);
            y0 = __hfma2(ev0, wch[k], y0);
            x1 = __hfma2(ev1, wgh[k], x1);
            y1 = __hfma2(ev1, wch[k], y1);
        }
        float2 xf0 = __half22float2(x0), yf0 = __half22float2(y0);
        float2 xf1 = __half22float2(x1), yf1 = __half22float2(y1);
        float m00 = fsigmoid(xf0.x) * fsoftplus(yf0.x);
        float m01 = fsigmoid(xf0.y) * fsoftplus(yf0.y);
        float m10 = fsigmoid(xf1.x) * fsoftplus(yf1.x);
        float m11 = fsigmoid(xf1.y) * fsoftplus(yf1.y);
        float p00 = __shfl_down_sync(0xffffffffu, m00, 1);
        float p01 = __shfl_down_sync(0xffffffffu, m01, 1);
        float p10 = __shfl_down_sync(0xffffffffu, m10, 1);
        float p11 = __shfl_down_sync(0xffffffffu, m11, 1);
        if ((l & 1) == 0) {
            red_add_v4(g_agg + (size_t)s0 * 64 + 2 * l, m00, m01, p00, p01);
            red_add_v4(g_agg + (size_t)s1 * 64 + 2 * l, m10, m11, p10, p11);
        }
    }
}

// ------- BN stats + finalize fused (last block computes scale/shift) --------
#define STATS_GRID 256
__global__ __launch_bounds__(256) void stats_k(const float* __restrict__ bg,
                                               const float* __restrict__ bb) {
    int tid = threadIdx.x;
    int q = tid & 15;
    int r = tid >> 4;
    float4 s = make_float4(0.f, 0.f, 0.f, 0.f);
    float4 s2 = make_float4(0.f, 0.f, 0.f, 0.f);
#pragma unroll 4
    for (int n = blockIdx.x * 16 + r; n < NN; n += STATS_GRID * 16) {
        float4 v = ((const float4*)g_agg)[(size_t)n * 16 + q];
        s.x += v.x; s.y += v.y; s.z += v.z; s.w += v.w;
        s2.x += v.x * v.x; s2.y += v.y * v.y; s2.z += v.z * v.z; s2.w += v.w * v.w;
    }
    __shared__ float4 sh[256], sh2[256];
    sh[tid] = s; sh2[tid] = s2;
    __syncthreads();
#pragma unroll
    for (int off = 128; off >= 16; off >>= 1) {
        if (tid < off) {
            float4 a = sh[tid + off], b = sh2[tid + off];
            sh[tid].x += a.x; sh[tid].y += a.y; sh[tid].z += a.z; sh[tid].w += a.w;
            sh2[tid].x += b.x; sh2[tid].y += b.y; sh2[tid].z += b.z; sh2[tid].w += b.w;
        }
        __syncthreads();
    }
    if (tid < 16) {
        float4 a = sh[tid], b = sh2[tid];
        atomicAdd(&g_stats[4 * tid + 0], a.x);
        atomicAdd(&g_stats[4 * tid + 1], a.y);
        atomicAdd(&g_stats[4 * tid + 2], a.z);
        atomicAdd(&g_stats[4 * tid + 3], a.w);
        atomicAdd(&g_stats[64 + 4 * tid + 0], b.x);
        atomicAdd(&g_stats[64 + 4 * tid + 1], b.y);
        atomicAdd(&g_stats[64 + 4 * tid + 2], b.z);
        atomicAdd(&g_stats[64 + 4 * tid + 3], b.w);
    }
    __threadfence();
    __shared__ int isLast;
    if (tid == 0) isLast = (atomicAdd(&g_ctr, 1) == STATS_GRID - 1);
    __syncthreads();
    if (isLast) {
        if (tid < 64) {
            float sv = g_stats[tid], sv2 = g_stats[64 + tid];
            float mean = sv * (1.f / NN);
            float var = sv2 * (1.f / NN) - mean * mean;
            float sc = bg[tid] * rsqrtf(fmaxf(var, 0.f) + 1e-5f);
            g_scale[tid] = sc;
            g_shift[tid] = bb[tid] - mean * sc;
            g_stats[tid] = 0.f;
            g_stats[64 + tid] = 0.f;
        }
        if (tid == 0) g_ctr = 0;
    }
}

// h = softplus(h + agg*scale + shift); re-zero agg; optional fused pooling
__global__ void upd_k(const int* __restrict__ gi, int doPool) {
    int i = blockIdx.x * 256 + threadIdx.x;
    if (i >= NN * 16) return;
    int j4 = (i & 15) * 4;
    float4 a = ((const float4*)g_agg)[i];
    ((float4*)g_agg)[i] = make_float4(0.f, 0.f, 0.f, 0.f);
    float4 h = ((const float4*)g_h)[i];
    float4 sc = *(const float4*)(g_scale + j4);
    float4 sf = *(const float4*)(g_shift + j4);
    h.x = fsoftplus(fmaf(a.x, sc.x, h.x + sf.x));
    h.y = fsoftplus(fmaf(a.y, sc.y, h.y + sf.y));
    h.z = fsoftplus(fmaf(a.z, sc.z, h.z + sf.z));
    h.w = fsoftplus(fmaf(a.w, sc.w, h.w + sf.w));
    if (doPool) {
        int n = i >> 4;
        int q = i & 15;
        int g = gi[n];
        red_add_v4(g_pool + g * 64 + 4 * q, h.x, h.y, h.z, h.w);
        if (q == 0) red_add_f(&g_cnt[g], 1.f);
    } else {
        ((float4*)g_h)[i] = h;
        __half2 h01 = __floats2half2_rn(h.x, h.y);
        __half2 h23 = __floats2half2_rn(h.z, h.w);
        uint2 packed;
        packed.x = *(unsigned*)&h01;
        packed.y = *(unsigned*)&h23;
        ((uint2*)g_hh)[i] = packed;
    }
}

// ---------------- final MLP; re-zeroes pool/cnt after reading ----------------
__global__ void mlp_k(const float* __restrict__ w1, const float* __restrict__ b1,
                      const float* __restrict__ w2, const float* __restrict__ b2,
                      const float* __restrict__ w3, const float* __restrict__ b3,
                      float* __restrict__ out) {
    int b = blockIdx.x;
    int t = threadIdx.x;  // 128 threads
    __shared__ float pm[64];
    __shared__ float s1[128];
    __shared__ float s2[64];
    __shared__ float red[128];
    if (t < 64) {
        float c = g_cnt[b];
        c = (c < 1.f) ? 1.f : c;
        pm[t] = g_pool[b * 64 + t] / c;
    }
    __syncthreads();
    if (t < 64) g_pool[b * 64 + t] = 0.f;
    if (t == 64) g_cnt[b] = 0.f;
    float a = b1[t];
#pragma unroll
    for (int k = 0; k < 64; k++) a = fmaf(pm[k], w1[k * 128 + t], a);
    s1[t] = fsoftplus(a);
    __syncthreads();
    if (t < 64) {
        float a2 = b2[t];
#pragma unroll
        for (int k = 0; k < 128; k++) a2 = fmaf(s1[k], w2[k * 64 + t], a2);
        s2[t] = fsoftplus(a2);
    }
    __syncthreads();
    float p = (t < 64) ? s2[t] * w3[t] : 0.f;
    red[t] = p;
    __syncthreads();
#pragma unroll
    for (int off = 64; off > 0; off >>= 1) {
        if (t < off) red[t] += red[t + off];
        __syncthreads();
    }
    if (t == 0) out[b] = red[0] + b3[0];
}

extern "C" void kernel_launch(void* const* d_in, const int* in_sizes, int n_in,
                              void* d_out, int out_size) {
    const float* nf  = (const float*)d_in[0];
    const int*   ei  = (const int*)d_in[1];
    const float* ef  = (const float*)d_in[2];
    const int*   gi  = (const int*)d_in[3];
    const float* ew  = (const float*)d_in[4];
    const float* eb  = (const float*)d_in[5];
    const float* gw  = (const float*)d_in[6];
    const float* gb  = (const float*)d_in[7];
    const float* cw  = (const float*)d_in[8];
    const float* cb  = (const float*)d_in[9];
    const float* bng = (const float*)d_in[10];
    const float* bnb = (const float*)d_in[11];
    const float* w1  = (const float*)d_in[12];
    const float* b1  = (const float*)d_in[13];
    const float* w2  = (const float*)d_in[14];
    const float* b2  = (const float*)d_in[15];
    const float* w3  = (const float*)d_in[16];
    const float* b3  = (const float*)d_in[17];
    float* out = (float*)d_out;
    const int* srcI = ei;
    const int* dstI = ei + EE;

    embed_k<<<(NN + 31) / 32, 256>>>(nf, ew, eb);
    for (int i = 0; i < 3; i++) {
        const float* gwi = gw + i * 138 * 64;
        const float* cwi = cw + i * 138 * 64;
        nodetf_k<<<(NN + NT_TILE - 1) / NT_TILE, 256>>>(gwi, cwi, gb + i * 64, cb + i * 64);
        edge_k<<<EE / 128, 256>>>(srcI, dstI, ef, gwi + 128 * 64, cwi + 128 * 64);
        stats_k<<<STATS_GRID, 256>>>(bng + i * 64, bnb + i * 64);
        upd_k<<<(NN * 16 + 255) / 256, 256>>>(gi, i == 2 ? 1 : 0);
    }
    mlp_k<<<BB, 128>>>(w1, b1, w2, b2, w3, b3, out);
}